// round 13
// baseline (speedup 1.0000x reference)
#include <cuda_runtime.h>
#include <cuda_fp16.h>
#include <cstdint>

#define HIDDEN   1024
#define EMB      512
#define NUM_OPS  8
#define BATCH    16384

#define BM 128
#define BN 128
#define BK 32
#define PIPE 4
#define NTHREADS 256

// smem row stride: 32 halves + 8 pad = 40 halves = 80 bytes (16B-aligned)
// LDSM 8-row phase: row i starts at word-bank (20*i)%32 -> 8 rows x 4 words tile all 32 banks
#define ROW_BYTES 80
#define A_STAGE_BYTES (BM * ROW_BYTES)     // 10240
#define B_STAGE_BYTES (BN * ROW_BYTES)     // 10240 (B stored [n][k])
#define STAGE_BYTES (A_STAGE_BYTES + B_STAGE_BYTES)
#define DYN_SMEM (PIPE * STAGE_BYTES)      // 81920

// ---- scratch (static device globals: no allocations allowed) ----
__device__ int    g_counts[NUM_OPS];
__device__ int    g_cursor[NUM_OPS];
__device__ int    g_offsets[NUM_OPS + 1];
__device__ int    g_perm[BATCH];
__device__ __half g_xh[(size_t)BATCH * HIDDEN];            // fp16 x
__device__ __half g_embh[NUM_OPS * EMB];                   // fp16 op_emb
__device__ __half g_w1t[(size_t)NUM_OPS * HIDDEN * 1536];  // fp16 W1^T [e][n][k]
__device__ __half g_w2t[(size_t)NUM_OPS * HIDDEN * 1024];  // fp16 W2^T [e][n][k]
__device__ __half g_h[(size_t)BATCH * HIDDEN];             // layer-1 out (sorted, fp16)

// ---- helpers ----
__device__ __forceinline__ uint32_t smem_u32(const void* p) {
    uint32_t a;
    asm("{ .reg .u64 t; cvta.to.shared.u64 t, %1; cvt.u32.u64 %0, t; }" : "=r"(a) : "l"(p));
    return a;
}
__device__ __forceinline__ void cp16(uint32_t s, const void* g) {
    asm volatile("cp.async.cg.shared.global [%0], [%1], 16;" :: "r"(s), "l"(g));
}
__device__ __forceinline__ void cp_commit() { asm volatile("cp.async.commit_group;"); }
template <int N> __device__ __forceinline__ void cp_wait() {
    asm volatile("cp.async.wait_group %0;" :: "n"(N));
}
__device__ __forceinline__ void ldsm4(uint32_t& d0, uint32_t& d1, uint32_t& d2, uint32_t& d3,
                                      uint32_t addr) {
    asm volatile("ldmatrix.sync.aligned.m8n8.x4.shared.b16 {%0,%1,%2,%3}, [%4];"
                 : "=r"(d0), "=r"(d1), "=r"(d2), "=r"(d3) : "r"(addr));
}
// fp16-accumulate mma: D(f16x2 x2) = A*B + C, chained in-register
__device__ __forceinline__ void mma_f16acc(uint32_t c[2],
                                           uint32_t a0, uint32_t a1, uint32_t a2, uint32_t a3,
                                           uint32_t b0, uint32_t b1) {
    asm volatile(
        "mma.sync.aligned.m16n8k16.row.col.f16.f16.f16.f16 "
        "{%0,%1}, {%2,%3,%4,%5}, {%6,%7}, {%0,%1};"
        : "+r"(c[0]), "+r"(c[1])
        : "r"(a0), "r"(a1), "r"(a2), "r"(a3), "r"(b0), "r"(b1));
}

// ---- routing ----
__global__ void init_kernel() { if (threadIdx.x < NUM_OPS) g_counts[threadIdx.x] = 0; }
__global__ void hist_kernel(const int* __restrict__ ops) {
    int i = blockIdx.x * blockDim.x + threadIdx.x;
    if (i < BATCH) atomicAdd(&g_counts[ops[i]], 1);
}
__global__ void scan_kernel() {
    int acc = 0;
    for (int e = 0; e < NUM_OPS; ++e) { g_offsets[e] = acc; g_cursor[e] = acc; acc += g_counts[e]; }
    g_offsets[NUM_OPS] = acc;
}
__global__ void scatter_kernel(const int* __restrict__ ops) {
    int i = blockIdx.x * blockDim.x + threadIdx.x;
    if (i < BATCH) { int pos = atomicAdd(&g_cursor[ops[i]], 1); g_perm[pos] = i; }
}

// ---- fp16 convert (elementwise, vectorized) ----
__global__ void cvt_kernel(const float4* __restrict__ in, uint2* __restrict__ out, int n4) {
    int i = blockIdx.x * blockDim.x + threadIdx.x;
    if (i < n4) {
        float4 v = in[i];
        __half2 h01 = __floats2half2_rn(v.x, v.y);
        __half2 h23 = __floats2half2_rn(v.z, v.w);
        uint2 o;
        o.x = *(uint32_t*)&h01;
        o.y = *(uint32_t*)&h23;
        out[i] = o;
    }
}

// ---- W [e][k][n] fp32 -> Wt [e][n][k] fp16 (32x32 tiles) ----
__global__ void transpose_cvt_kernel(const float* __restrict__ W, __half* __restrict__ Wt, int K) {
    __shared__ float t[32][33];
    const int e = blockIdx.z;
    const int n0 = blockIdx.x * 32, k0 = blockIdx.y * 32;
    const float* Wb = W + (size_t)e * K * HIDDEN;
    __half* Wtb = Wt + (size_t)e * HIDDEN * K;
    const int tid = threadIdx.x;   // 256
#pragma unroll
    for (int i = 0; i < 4; ++i) {
        int idx = tid + 256 * i;
        int n = idx & 31, k = idx >> 5;
        t[k][n] = Wb[(size_t)(k0 + k) * HIDDEN + n0 + n];
    }
    __syncthreads();
#pragma unroll
    for (int i = 0; i < 2; ++i) {
        int idx = tid + 256 * i;
        int nl = idx >> 4, p = idx & 15;
        __half2 h = __floats2half2_rn(t[2 * p][nl], t[2 * p + 1][nl]);
        *(__half2*)(Wtb + (size_t)(n0 + nl) * K + k0 + 2 * p) = h;
    }
}

// ---- grouped GEMM: fp16 mma (fp16 acc, fp32 promote every 2 kt), 4-stage cp.async ----
template <int LAYER>
__global__ __launch_bounds__(NTHREADS) void gemm_tc(
    const float* __restrict__ bias, float* __restrict__ out)
{
    constexpr int K  = (LAYER == 1) ? 1536 : 1024;
    constexpr int KT = K / BK;           // 48 / 32 (even -> promote at odd kt covers all)

    const int e = blockIdx.z;
    const int seg_lo = g_offsets[e];
    const int seg_hi = g_offsets[e + 1];
    const int row0 = seg_lo + blockIdx.y * BM;
    if (row0 >= seg_hi) return;
    const int n0 = blockIdx.x * BN;

    extern __shared__ char dyn[];
    const uint32_t sbase = smem_u32(dyn);

    const int tid  = threadIdx.x;
    const int lane = tid & 31;
    const int warp = tid >> 5;
    const int wm = (warp & 1) * 64;    // 2 warps along M
    const int wn = (warp >> 1) * 32;   // 4 warps along N
    const int r  = lane >> 2;
    const int cc = lane & 3;

    // A loader: row = tid>>1 (0..127), two 16B chunks (16 halves) per thread
    const int arow_loc = tid >> 1;
    const int ac0 = (tid & 1) * 2;
    int arow = row0 + arow_loc;
    if (arow > seg_hi - 1) arow = seg_hi - 1;      // clamp; masked at store
    const __half* Abase;
    if (LAYER == 1) Abase = g_xh + (size_t)g_perm[arow] * HIDDEN;
    else            Abase = g_h + (size_t)arow * HIDDEN;
    const __half* Ebase = g_embh + e * EMB;
    const uint32_t a_soff = (uint32_t)(arow_loc * ROW_BYTES + ac0 * 16);

    // B loader: n-row = tid>>1, two 16B chunks per thread; B stored [n][k] K-major
    const __half* Wt = (LAYER == 1) ? g_w1t : g_w2t;
    const __half* Bbase = Wt + ((size_t)e * HIDDEN + n0 + arow_loc) * K + ac0 * 8;
    const uint32_t b_soff = (uint32_t)(A_STAGE_BYTES + arow_loc * ROW_BYTES + ac0 * 16);

    auto load_stage = [&](int s) {
        const int kb = s * BK;
        const uint32_t st = sbase + (uint32_t)((s % PIPE) * STAGE_BYTES);
        const bool emb_stage = (LAYER == 1) && (kb >= HIDDEN);
        const __half* asrc = emb_stage ? (Ebase + (kb - HIDDEN) + ac0 * 8)
                                       : (Abase + kb + ac0 * 8);
#pragma unroll
        for (int j = 0; j < 2; ++j) cp16(st + a_soff + j * 16u, asrc + j * 8);
        const __half* bsrc = Bbase + kb;
#pragma unroll
        for (int j = 0; j < 2; ++j) cp16(st + b_soff + j * 16u, bsrc + j * 8);
    };

    // ldmatrix per-thread base offsets (within a stage)
    const uint32_t a_lds = (uint32_t)((wm + (lane & 15)) * ROW_BYTES + ((lane >> 4) & 1) * 16);
    const uint32_t b_lds = (uint32_t)(A_STAGE_BYTES +
                                      (wn + ((lane >> 4) & 1) * 8 + (lane & 7)) * ROW_BYTES +
                                      ((lane >> 3) & 1) * 16);

    float    c32[4][4][4];              // master fp32 accumulators
    uint32_t c16[4][4][2];              // fp16x2 chain accumulators (4-mma window)
#pragma unroll
    for (int mt = 0; mt < 4; ++mt)
#pragma unroll
        for (int nt = 0; nt < 4; ++nt) {
#pragma unroll
            for (int i = 0; i < 4; ++i) c32[mt][nt][i] = 0.f;
            c16[mt][nt][0] = 0u; c16[mt][nt][1] = 0u;
        }

    auto compute = [&](int buf) {
        const uint32_t sb = sbase + (uint32_t)buf * STAGE_BYTES;
#pragma unroll
        for (int ks = 0; ks < 2; ++ks) {           // 2 x K=16 slices cover BK=32
            const uint32_t ko = (uint32_t)(ks * 32);
            uint32_t af[4][4];
            uint32_t bf[4][2];
#pragma unroll
            for (int mt = 0; mt < 4; ++mt)
                ldsm4(af[mt][0], af[mt][1], af[mt][2], af[mt][3],
                      sb + a_lds + (uint32_t)(mt * 16 * ROW_BYTES) + ko);
#pragma unroll
            for (int p = 0; p < 2; ++p)
                ldsm4(bf[2 * p][0], bf[2 * p][1], bf[2 * p + 1][0], bf[2 * p + 1][1],
                      sb + b_lds + (uint32_t)(p * 16 * ROW_BYTES) + ko);
#pragma unroll
            for (int mt = 0; mt < 4; ++mt)
#pragma unroll
                for (int nt = 0; nt < 4; ++nt)
                    mma_f16acc(c16[mt][nt], af[mt][0], af[mt][1], af[mt][2], af[mt][3],
                               bf[nt][0], bf[nt][1]);
        }
    };

    // promote fp16 chains into fp32 masters, reset chains
    auto promote = [&]() {
#pragma unroll
        for (int mt = 0; mt < 4; ++mt)
#pragma unroll
            for (int nt = 0; nt < 4; ++nt) {
                float2 lo = __half22float2(*(__half2*)&c16[mt][nt][0]);  // row r,  cols 2cc,2cc+1
                float2 hi = __half22float2(*(__half2*)&c16[mt][nt][1]);  // row r+8
                c32[mt][nt][0] += lo.x; c32[mt][nt][1] += lo.y;
                c32[mt][nt][2] += hi.x; c32[mt][nt][3] += hi.y;
                c16[mt][nt][0] = 0u; c16[mt][nt][1] = 0u;
            }
    };

    // prologue: 3 stages in flight
    load_stage(0); cp_commit();
    load_stage(1); cp_commit();
    load_stage(2); cp_commit();

    for (int kt = 0; kt < KT; ++kt) {
        cp_wait<2>();                 // stage kt resident; kt+1, kt+2 still in flight
        __syncthreads();              // all warps see stage kt; all done reading buf (kt+3)%4
        if (kt + 3 < KT) load_stage(kt + 3);
        cp_commit();                  // uniform (possibly empty) commit keeps group counts fixed
        compute(kt % PIPE);
        if (kt & 1) promote();        // every 2 kt = 4-mma fp16 chain; KT even -> covers all
    }

    // epilogue: bias + relu; layer1 -> fp16 g_h, layer2 -> fp32 scatter
    const float* brow = bias + e * HIDDEN;
#pragma unroll
    for (int mt = 0; mt < 4; ++mt) {
        const int rbase = row0 + wm + mt * 16 + r;
#pragma unroll
        for (int half = 0; half < 2; ++half) {
            const int row = rbase + half * 8;
            if (row >= seg_hi) continue;
#pragma unroll
            for (int nt = 0; nt < 4; ++nt) {
                const int col = n0 + wn + nt * 8 + 2 * cc;
                float v0 = c32[mt][nt][half * 2 + 0] + __ldg(brow + col);
                float v1 = c32[mt][nt][half * 2 + 1] + __ldg(brow + col + 1);
                v0 = v0 > 0.f ? v0 : 0.f;
                v1 = v1 > 0.f ? v1 : 0.f;
                if (LAYER == 1) {
                    __half2 h = __floats2half2_rn(v0, v1);
                    *(__half2*)(g_h + (size_t)row * HIDDEN + col) = h;
                } else {
                    *(float2*)(out + (size_t)g_perm[row] * HIDDEN + col) = make_float2(v0, v1);
                }
            }
        }
    }
}

extern "C" void kernel_launch(void* const* d_in, const int* in_sizes, int n_in,
                              void* d_out, int out_size) {
    const float* x      = (const float*)d_in[0];
    const int*   ops    = (const int*)  d_in[1];
    const float* op_emb = (const float*)d_in[2];
    const float* W1     = (const float*)d_in[3];
    const float* b1     = (const float*)d_in[4];
    const float* W2     = (const float*)d_in[5];
    const float* b2     = (const float*)d_in[6];
    float* out = (float*)d_out;

    cudaFuncSetAttribute(gemm_tc<1>, cudaFuncAttributeMaxDynamicSharedMemorySize, DYN_SMEM);
    cudaFuncSetAttribute(gemm_tc<2>, cudaFuncAttributeMaxDynamicSharedMemorySize, DYN_SMEM);

    // routing
    init_kernel<<<1, 32>>>();
    hist_kernel<<<BATCH / 256, 256>>>(ops);
    scan_kernel<<<1, 1>>>();
    scatter_kernel<<<BATCH / 256, 256>>>(ops);

    // fp16 conversion + weight transpose
    {
        __half* xh;  cudaGetSymbolAddress((void**)&xh,  g_xh);
        __half* eh;  cudaGetSymbolAddress((void**)&eh,  g_embh);
        __half* w1t; cudaGetSymbolAddress((void**)&w1t, g_w1t);
        __half* w2t; cudaGetSymbolAddress((void**)&w2t, g_w2t);
        int n4;
        n4 = BATCH * HIDDEN / 4;
        cvt_kernel<<<(n4 + 255) / 256, 256>>>((const float4*)x, (uint2*)xh, n4);
        n4 = NUM_OPS * EMB / 4;
        cvt_kernel<<<(n4 + 255) / 256, 256>>>((const float4*)op_emb, (uint2*)eh, n4);
        transpose_cvt_kernel<<<dim3(HIDDEN / 32, 1536 / 32, NUM_OPS), 256>>>(W1, w1t, 1536);
        transpose_cvt_kernel<<<dim3(HIDDEN / 32, 1024 / 32, NUM_OPS), 256>>>(W2, w2t, 1024);
    }

    dim3 grid(HIDDEN / BN, BATCH / BM, NUM_OPS);
    gemm_tc<1><<<grid, NTHREADS, DYN_SMEM>>>(b1, nullptr);
    gemm_tc<2><<<grid, NTHREADS, DYN_SMEM>>>(b2, out);
}